// round 14
// baseline (speedup 1.0000x reference)
#include <cuda_runtime.h>
#include <cstdint>

// Problem constants (fixed by the reference)
#define VOCAB 32000
#define D_EMB 768
#define SEQ   2048
#define BATCH 16
#define F8    (D_EMB / 8)        // 96 float8 per row

// Geometry: grid = (256, 3, 2), 256 threads (8 warps).
//   blockIdx.x -> chunk of 8 s-rows
//   blockIdx.y -> slice of 32 float8 columns (256 d values)
//   blockIdx.z -> batch half; warp w -> batch blockIdx.z*8 + w
// Each lane owns ONE 32-byte float8 column; a warp-store is 1024B contiguous
// issued as a single st.global.v8.b32 (STG.E.256, sm_100+): half the store
// instructions / LSU slots of the float4 version, bigger aligned bursts on
// the write path (which R10-R13 showed to be the binding resource).
#define S_PER_BLK 8
#define C8_PER_BLK 32             // float8 columns per block
#define D_PER_BLK (C8_PER_BLK * 8) // 256
#define B_PER_BLK 8
#define THREADS   256

// ---- 256-bit global memory access (sm_100+/sm_103a) ----------------------
__device__ __forceinline__ void ldg256(const float* __restrict__ p, float v[8]) {
    asm volatile("ld.global.nc.v8.b32 {%0,%1,%2,%3,%4,%5,%6,%7}, [%8];"
                 : "=f"(v[0]), "=f"(v[1]), "=f"(v[2]), "=f"(v[3]),
                   "=f"(v[4]), "=f"(v[5]), "=f"(v[6]), "=f"(v[7])
                 : "l"(p));
}
__device__ __forceinline__ void stg256(float* __restrict__ p, const float v[8]) {
    asm volatile("st.global.v8.b32 [%0], {%1,%2,%3,%4,%5,%6,%7,%8};"
                 :: "l"(p),
                    "f"(v[0]), "f"(v[1]), "f"(v[2]), "f"(v[3]),
                    "f"(v[4]), "f"(v[5]), "f"(v[6]), "f"(v[7])
                 : "memory");
}

// ---------------------------------------------------------------------------
// Semantics (from the reference's where() inversion):
//   out[b,s,d] = pe[s,d]
//              + (input_ids[b,s]==0     ? W_tok[d,0]+b_tok[d] : 0)
//              + (segment_label[b,s]==0 ? W_seg[d,0]+b_seg[d] : 0)
//
// R13 -> R14 changes:
//  * 256-bit stores/loads (st.global.v8 / ld.global.nc.v8): warp = 1024B
//    contiguous per instruction.
//  * evict-normal stores (no __stcs): in the steady-state timed loop each
//    replay overwrites the previous replay's dirty L2 lines in place instead
//    of forcing early writebacks.
//  * Layout otherwise = R13 (warp-per-batch, s-inner, page-local stores).
// ---------------------------------------------------------------------------
__global__ void __launch_bounds__(THREADS)
bebert_fused_kernel(const int*   __restrict__ input_ids,
                    const int*   __restrict__ segment_label,
                    const float* __restrict__ W_tok,
                    const float* __restrict__ b_tok,
                    const float* __restrict__ W_seg,
                    const float* __restrict__ b_seg,
                    const float* __restrict__ pe,
                    float*       __restrict__ out)
{
    __shared__ __align__(32) float s_tok[D_PER_BLK];
    __shared__ __align__(32) float s_seg[D_PER_BLK];

    const int t      = threadIdx.x;
    const int w      = t >> 5;                   // warp 0..7
    const int l      = t & 31;                   // lane = float8 column
    const int s0     = blockIdx.x * S_PER_BLK;
    const int cslice = blockIdx.y;               // 0..2
    const int b      = blockIdx.z * B_PER_BLK + w;
    const int d0     = cslice * D_PER_BLK;

    // --- prep: combined vectors for this slice (all 256 threads, 1 d each) ---
    {
        const int d = d0 + t;
        s_tok[t] = __ldg(W_tok + (size_t)d * VOCAB) + __ldg(b_tok + d);
        s_seg[t] = __ldg(W_seg + (size_t)d * 3)     + __ldg(b_seg + d);
    }

    // --- masks in registers: 8 s-predicates for this warp's batch ---
    // lanes load rows s0 + (l & 7); ballot bit sr = predicate for row s0+sr.
    unsigned tokm, segm;
    {
        const int row = b * SEQ + s0 + (l & 7);
        tokm = __ballot_sync(0xFFFFFFFFu, __ldg(input_ids     + row) == 0);
        segm = __ballot_sync(0xFFFFFFFFu, __ldg(segment_label + row) == 0);
    }
    __syncthreads();

    // This lane's float8 of the combined vectors (one-time smem read).
    float tv[8], sv[8];
#pragma unroll
    for (int i = 0; i < 8; ++i) {
        tv[i] = s_tok[l * 8 + i];
        sv[i] = s_seg[l * 8 + i];
    }

    const float* perow = pe
        + (size_t)s0 * D_EMB + (size_t)(cslice * C8_PER_BLK + l) * 8;
    float* o = out
        + ((size_t)b * SEQ + s0) * D_EMB + (size_t)(cslice * C8_PER_BLK + l) * 8;

#pragma unroll
    for (int sr = 0; sr < S_PER_BLK; ++sr) {
        float r[8];
        ldg256(perow + (size_t)sr * D_EMB, r);   // L1-hit for 7 of 8 warps
        const bool th = (tokm >> sr) & 1u;
        const bool sh = (segm >> sr) & 1u;
        if (th) {
#pragma unroll
            for (int i = 0; i < 8; ++i) r[i] += tv[i];
        }
        if (sh) {
#pragma unroll
            for (int i = 0; i < 8; ++i) r[i] += sv[i];
        }
        stg256(o + (size_t)sr * D_EMB, r);       // 1024B/warp, page-local
    }
}

// ---------------------------------------------------------------------------
// Launch. Input order (metadata): input_ids, segment_label, W_tok, b_tok,
// W_seg, b_seg, pe. ids arrive as int32 (jax x64 disabled). Output fp32.
// ---------------------------------------------------------------------------
extern "C" void kernel_launch(void* const* d_in, const int* in_sizes, int n_in,
                              void* d_out, int out_size) {
    const int*   input_ids     = (const int*)  d_in[0];
    const int*   segment_label = (const int*)  d_in[1];
    const float* W_tok         = (const float*)d_in[2];
    const float* b_tok         = (const float*)d_in[3];
    const float* W_seg         = (const float*)d_in[4];
    const float* b_seg         = (const float*)d_in[5];
    const float* pe            = (const float*)d_in[6];
    float*       out           = (float*)d_out;

    dim3 grid(SEQ / S_PER_BLK, F8 / C8_PER_BLK, BATCH / B_PER_BLK); // (256,3,2)
    bebert_fused_kernel<<<grid, THREADS>>>(
        input_ids, segment_label, W_tok, b_tok, W_seg, b_seg, pe, out);
}

// round 15
// speedup vs baseline: 1.0227x; 1.0227x over previous
#include <cuda_runtime.h>
#include <cstdint>

// Problem constants (fixed by the reference)
#define VOCAB 32000
#define D_EMB 768
#define SEQ   2048
#define BATCH 16
#define F4    (D_EMB / 4)        // 192 float4 per row

// Geometry (= R10, best measured wall): grid (512, 3), 256 threads.
//   blockIdx.x -> chunk of 4 s-rows
//   blockIdx.y -> slice of 64 f4 columns (256 d values)
// Warp = one s-row x 32 f4 columns -> every store is 512B contiguous.
#define S_PER_BLK 4
#define C_PER_BLK 64              // float4 columns per block
#define D_PER_BLK (C_PER_BLK * 4) // 256
#define THREADS   (S_PER_BLK * C_PER_BLK) // 256

// ---------------------------------------------------------------------------
// Semantics (from the reference's where() inversion):
//   out[b,s,d] = pe[s,d]
//              + (input_ids[b,s]==0     ? W_tok[d,0]+b_tok[d] : 0)
//              + (segment_label[b,s]==0 ? W_seg[d,0]+b_seg[d] : 0)
//
// R15 = union of the two 20.99us configs:
//  * R10 geometry / store order (b-innermost, 512B warp stores).
//  * R12 register ballot masks (no smem mask table, no hot-path LDS).
//  * plain evict-normal STG (cs / wt / v8 all measured neutral or worse).
//  * L1::no_allocate on the one-shot strided prep gather (don't pollute L1).
// Steady-state model: ~101MB mandatory writes at ~5.3TB/s + ~2us replay
// overhead => ~21us floor; this config locks in the best-measured point.
// ---------------------------------------------------------------------------
__global__ void __launch_bounds__(THREADS)
bebert_fused_kernel(const int*   __restrict__ input_ids,
                    const int*   __restrict__ segment_label,
                    const float* __restrict__ W_tok,
                    const float* __restrict__ b_tok,
                    const float* __restrict__ W_seg,
                    const float* __restrict__ b_seg,
                    const float* __restrict__ pe,
                    float*       __restrict__ out)
{
    __shared__ __align__(16) float s_tok[D_PER_BLK];
    __shared__ __align__(16) float s_seg[D_PER_BLK];

    const int t      = threadIdx.x;
    const int w      = t >> 5;                 // warp 0..7
    const int l      = t & 31;                 // lane
    const int s0     = blockIdx.x * S_PER_BLK;
    const int cslice = blockIdx.y;             // 0..2
    const int d0     = cslice * D_PER_BLK;

    // --- prep: combined vectors for this slice (256 threads, 1 d each).
    // One-shot strided gather; keep it out of L1 (used once per block).
    {
        const int d = d0 + t;
        float wt, ws;
        asm volatile("ld.global.nc.L1::no_allocate.f32 %0, [%1];"
                     : "=f"(wt) : "l"(W_tok + (size_t)d * VOCAB));
        asm volatile("ld.global.nc.L1::no_allocate.f32 %0, [%1];"
                     : "=f"(ws) : "l"(W_seg + (size_t)d * 3));
        s_tok[t] = wt + __ldg(b_tok + d);
        s_seg[t] = ws + __ldg(b_seg + d);
    }

    // --- masks in registers: each warp ballots the 4 rows x 16 batches.
    // Lane layout: local s-row r = l >> 4 ... need 4 rows x 16 b = 64 preds;
    // use two ballots: rows {0,1} and rows {2,3}. Bit (r_in_pair*16 + b).
    unsigned tok01, seg01, tok23, seg23;
    {
        const int b   = l & 15;
        const int rA  = (l >> 4);              // 0..1
        const int rowA = b * SEQ + s0 + rA;
        tok01 = __ballot_sync(0xFFFFFFFFu, __ldg(input_ids     + rowA) == 0);
        seg01 = __ballot_sync(0xFFFFFFFFu, __ldg(segment_label + rowA) == 0);
        const int rowB = rowA + 2;             // rows 2..3
        tok23 = __ballot_sync(0xFFFFFFFFu, __ldg(input_ids     + rowB) == 0);
        seg23 = __ballot_sync(0xFFFFFFFFu, __ldg(segment_label + rowB) == 0);
    }
    __syncthreads();

    // Worker mapping: warp w -> s-row (w >> 1), column half (w & 1).
    const int local_s = w >> 1;                // 0..3
    const int c_local = ((w & 1) << 5) + l;    // 0..63
    const int s       = s0 + local_s;
    const int c       = cslice * C_PER_BLK + c_local;

    const unsigned tokw = (local_s < 2 ? tok01 : tok23) >> ((local_s & 1) << 4);
    const unsigned segw = (local_s < 2 ? seg01 : seg23) >> ((local_s & 1) << 4);

    const float4 tv = reinterpret_cast<const float4*>(s_tok)[c_local];
    const float4 sv = reinterpret_cast<const float4*>(s_seg)[c_local];
    const float4 p  = reinterpret_cast<const float4*>(pe + (size_t)s * D_EMB)[c];

    float4* out4 = reinterpret_cast<float4*>(out) + (size_t)s * F4 + c;

#pragma unroll
    for (int b = 0; b < BATCH; ++b) {
        float4 r = p;
        if ((tokw >> b) & 1u) { r.x += tv.x; r.y += tv.y; r.z += tv.z; r.w += tv.w; }
        if ((segw >> b) & 1u) { r.x += sv.x; r.y += sv.y; r.z += sv.z; r.w += sv.w; }
        out4[(size_t)b * (SEQ * F4)] = r;      // coalesced 512B per warp
    }
}

// ---------------------------------------------------------------------------
// Launch. Input order (metadata): input_ids, segment_label, W_tok, b_tok,
// W_seg, b_seg, pe. ids arrive as int32 (jax x64 disabled). Output fp32.
// ---------------------------------------------------------------------------
extern "C" void kernel_launch(void* const* d_in, const int* in_sizes, int n_in,
                              void* d_out, int out_size) {
    const int*   input_ids     = (const int*)  d_in[0];
    const int*   segment_label = (const int*)  d_in[1];
    const float* W_tok         = (const float*)d_in[2];
    const float* b_tok         = (const float*)d_in[3];
    const float* W_seg         = (const float*)d_in[4];
    const float* b_seg         = (const float*)d_in[5];
    const float* pe            = (const float*)d_in[6];
    float*       out           = (float*)d_out;

    dim3 grid(SEQ / S_PER_BLK, F4 / C_PER_BLK);   // (512, 3)
    bebert_fused_kernel<<<grid, THREADS>>>(
        input_ids, segment_label, W_tok, b_tok, W_seg, b_seg, pe, out);
}

// round 16
// speedup vs baseline: 1.1023x; 1.0779x over previous
#include <cuda_runtime.h>
#include <cstdint>

// Problem constants (fixed by the reference)
#define VOCAB 32000
#define D_EMB 768
#define SEQ   2048
#define BATCH 16
#define F4    (D_EMB / 4)        // 192 float4 per row

// Geometry (champion, R10 = 20.99us): grid = (512, 3), 256 threads.
//   blockIdx.x -> chunk of 4 s-rows
//   blockIdx.y -> one of 3 c-slices (64 float4 = 256 d values)
// 256 threads = 4 s-rows x 64 c-columns; warp stores are 512B contiguous.
#define S_PER_BLK 4
#define C_PER_BLK 64              // float4 columns per block
#define D_PER_BLK (C_PER_BLK * 4) // 256
#define THREADS   (S_PER_BLK * C_PER_BLK) // 256

// ---------------------------------------------------------------------------
// Semantics (from the reference's where() inversion):
//   out[b,s,d] = pe[s,d]
//              + (input_ids[b,s]==0     ? W_tok[d,0]+b_tok[d] : 0)
//              + (segment_label[b,s]==0 ? W_seg[d,0]+b_seg[d] : 0)
//
// Final form = the measured champion config (R10). Steady-state model
// (validated by 8 geometry experiments landing in one 2us band, with cold
// ncu time anti-correlated to wall): every graph replay forces ~100.7MB of
// dirty-L2 writebacks to DRAM; at ~5TB/s write-stream that is ~20.1us + ~1us
// replay overhead = the 20.99us floor. The bytes are mandatory, so the
// plainest maximally-coalesced store pattern wins; all "improvements" that
// only moved cold-cache metrics (v8 stores, __stcs, no_allocate, register
// mask selects, single-wave grids, s-inner ordering) regressed or tied.
// ---------------------------------------------------------------------------
__global__ void __launch_bounds__(THREADS)
bebert_fused_kernel(const int*   __restrict__ input_ids,
                    const int*   __restrict__ segment_label,
                    const float* __restrict__ W_tok,
                    const float* __restrict__ b_tok,
                    const float* __restrict__ W_seg,
                    const float* __restrict__ b_seg,
                    const float* __restrict__ pe,
                    float*       __restrict__ out)
{
    __shared__ __align__(16) float s_tok[D_PER_BLK];
    __shared__ __align__(16) float s_seg[D_PER_BLK];
    // Packed predicate words: word w covers s-rows {2w, 2w+1};
    // bit layout: bit (r_in_pair*16 + b).
    __shared__ unsigned s_tokbits[2];
    __shared__ unsigned s_segbits[2];

    const int t      = threadIdx.x;
    const int s0     = blockIdx.x * S_PER_BLK;
    const int cslice = blockIdx.y;           // 0..2
    const int d0     = cslice * D_PER_BLK;   // first d of this slice

    // --- prep: combined vectors for this slice (1 element per thread) ---
    {
        const int d = d0 + t;                // t < 256 == D_PER_BLK
        s_tok[t] = __ldg(W_tok + (size_t)d * VOCAB) + __ldg(b_tok + d);
        s_seg[t] = __ldg(W_seg + (size_t)d * 3)     + __ldg(b_seg + d);
    }

    // --- masks via warp ballot: warps 0,1 each cover 2 s-rows x 16 b ---
    if (t < 64) {
        const int w = t >> 5;                // warp: rows {2w, 2w+1}
        const int l = t & 31;
        const int r = (w << 1) + (l >> 4);   // local s-row 0..3
        const int b = l & 15;
        const int row = b * SEQ + s0 + r;
        const unsigned tokv = __ballot_sync(0xFFFFFFFFu,
                                            __ldg(input_ids     + row) == 0);
        const unsigned segv = __ballot_sync(0xFFFFFFFFu,
                                            __ldg(segment_label + row) == 0);
        if (l == 0) { s_tokbits[w] = tokv; s_segbits[w] = segv; }
    }
    __syncthreads();

    const int local_s = t >> 6;              // 0..3
    const int c_local = t & 63;              // 0..63
    const int s       = s0 + local_s;
    const int c       = cslice * C_PER_BLK + c_local;

    const float4 tv = reinterpret_cast<const float4*>(s_tok)[c_local];
    const float4 sv = reinterpret_cast<const float4*>(s_seg)[c_local];
    const float4 p  = reinterpret_cast<const float4*>(pe + (size_t)s * D_EMB)[c];

    const unsigned tokw = s_tokbits[local_s >> 1] >> ((local_s & 1) << 4);
    const unsigned segw = s_segbits[local_s >> 1] >> ((local_s & 1) << 4);

    float4* out4 = reinterpret_cast<float4*>(out) + (size_t)s * F4 + c;

#pragma unroll
    for (int b = 0; b < BATCH; ++b) {
        float4 r = p;
        if ((tokw >> b) & 1u) { r.x += tv.x; r.y += tv.y; r.z += tv.z; r.w += tv.w; }
        if ((segw >> b) & 1u) { r.x += sv.x; r.y += sv.y; r.z += sv.z; r.w += sv.w; }
        out4[(size_t)b * (SEQ * F4)] = r;    // coalesced 512B per warp
    }
}

// ---------------------------------------------------------------------------
// Launch. Input order (metadata): input_ids, segment_label, W_tok, b_tok,
// W_seg, b_seg, pe. ids arrive as int32 (jax x64 disabled). Output fp32.
// ---------------------------------------------------------------------------
extern "C" void kernel_launch(void* const* d_in, const int* in_sizes, int n_in,
                              void* d_out, int out_size) {
    const int*   input_ids     = (const int*)  d_in[0];
    const int*   segment_label = (const int*)  d_in[1];
    const float* W_tok         = (const float*)d_in[2];
    const float* b_tok         = (const float*)d_in[3];
    const float* W_seg         = (const float*)d_in[4];
    const float* b_seg         = (const float*)d_in[5];
    const float* pe            = (const float*)d_in[6];
    float*       out           = (float*)d_out;

    dim3 grid(SEQ / S_PER_BLK, F4 / C_PER_BLK);   // (512, 3)
    bebert_fused_kernel<<<grid, THREADS>>>(
        input_ids, segment_label, W_tok, b_tok, W_seg, b_seg, pe, out);
}